// round 5
// baseline (speedup 1.0000x reference)
#include <cuda_runtime.h>

#define B_SZ    16384
#define NL      131072
#define THREADS 256
#define CELL_BLOCKS 448                // 448*256 threads, 7 cells each
#define CELL_THREADS (CELL_BLOCKS * THREADS)   // 114688
#define LABEL_BLOCKS 512               // 512*256 = 131072 = NL
#define NBLOCKS (CELL_BLOCKS + LABEL_BLOCKS)   // 960
#define NCLS    20

__device__ double       g_acc   = 0.0;
__device__ unsigned int g_count = 0;

__device__ __forceinline__ float iou_pair(float ax, float ay, float aw, float ah,
                                          float gx, float gy, float gw, float gh) {
    float ax1 = ax - aw * 0.5f, ax2 = ax + aw * 0.5f;
    float ay1 = ay - ah * 0.5f, ay2 = ay + ah * 0.5f;
    float gx1 = gx - gw * 0.5f, gx2 = gx + gw * 0.5f;
    float gy1 = gy - gh * 0.5f, gy2 = gy + gh * 0.5f;
    float iw = fmaxf(0.0f, fminf(ax2, gx2) - fmaxf(ax1, gx1));
    float ih = fmaxf(0.0f, fminf(ay2, gy2) - fmaxf(ay1, gy1));
    float inter = iw * ih;
    float uni = aw * ah + gw * gh - inter;
    return inter / (uni + 1e-6f);
}

__global__ void __launch_bounds__(THREADS)
yolo_loss_kernel(const float* __restrict__ out, const float* __restrict__ labels,
                 float* __restrict__ result) {
    __shared__ float2   stage[THREADS][17];   // 17 float2 row stride: <=2-way conflicts
    __shared__ unsigned cellbase[THREADS];    // float-offset of each label's cell

    float local = 0.0f;

    if (blockIdx.x < CELL_BLOCKS) {
        // ---- no-object term: 7 independent strided float2 loads per thread ----
        unsigned base = blockIdx.x * THREADS + threadIdx.x;
        float2 v[7];
        #pragma unroll
        for (int k = 0; k < 7; k++) {
            unsigned cell = base + k * CELL_THREADS;
            v[k] = *reinterpret_cast<const float2*>(out + (size_t)cell * 30 + 20);
        }
        #pragma unroll
        for (int k = 0; k < 7; k++)
            local += v[k].x * v[k].x + v[k].y * v[k].y;
        local *= 0.5f;
    } else {
        // ---- per-label term: smem-staged coalesced gather ----
        int t = threadIdx.x;
        unsigned i = (blockIdx.x - CELL_BLOCKS) * THREADS + t;   // < NL
        const float2* Lp = reinterpret_cast<const float2*>(labels + (size_t)i * 6);
        float2 l0 = __ldg(Lp + 0);   // b, cls
        float2 l1 = __ldg(Lp + 1);   // gx, gy
        float2 l2 = __ldg(Lp + 2);   // gw, gh
        int b = (int)l0.x;
        int c = (int)l0.y;
        float gx = l1.x, gy = l1.y, gw = l2.x, gh = l2.y;

        float rowf = floorf(gx * 7.0f);
        float colf = floorf(gy * 7.0f);
        int row = (int)rowf, col = (int)colf;

        cellbase[t] = ((unsigned)b * 49u + (unsigned)(row * 7 + col)) * 30u;
        __syncthreads();

        // Gather: group g (16 threads) fetches label j's 15 contiguous float2.
        // Per warp-LDG: 2 labels x ~2 lines = ~4 wavefronts (vs 32 scattered).
        int g = t >> 4, m = t & 15;
        #pragma unroll
        for (int p = 0; p < 16; p++) {
            int j = p * 16 + g;
            if (m < 15) {
                const float2* src =
                    reinterpret_cast<const float2*>(out + cellbase[j]) + m;
                stage[j][m] = __ldg(src);
            }
        }
        __syncthreads();

        float pv[30];
        #pragma unroll
        for (int k = 0; k < 15; k++) {
            float2 v = stage[t][k];
            pv[2 * k]     = v.x;
            pv[2 * k + 1] = v.y;
        }

        // class loss
        float cls = 0.0f;
        #pragma unroll
        for (int k = 0; k < NCLS; k++) {
            float d = pv[k] - (k == c ? 1.0f : 0.0f);
            cls += d * d;
        }

        const float inv_s = 1.0f / 7.0f;
        float iou1 = iou_pair((rowf + pv[22]) * inv_s, (colf + pv[23]) * inv_s,
                              pv[24], pv[25], gx, gy, gw, gh);
        float iou2 = iou_pair((rowf + pv[26]) * inv_s, (colf + pv[27]) * inv_s,
                              pv[28], pv[29], gx, gy, gw, gh);
        bool use1 = (iou1 >= iou2);

        float gcx = gx * 7.0f - rowf;
        float gcy = gy * 7.0f - colf;

        float px = use1 ? pv[22] : pv[26];
        float py = use1 ? pv[23] : pv[27];
        float pw = use1 ? pv[24] : pv[28];
        float ph = use1 ? pv[25] : pv[29];

        const float eps = 1e-6f;
        float dx = px - gcx;
        float dy = py - gcy;
        float dw = sqrtf(pw + eps) - sqrtf(gw + eps);
        float dh = sqrtf(ph + eps) - sqrtf(gh + eps);
        float coor = 5.0f * (dx * dx + dy * dy + dw * dw + dh * dh);

        float cp = use1 ? pv[20] : pv[21];
        float ct = use1 ? iou1 : iou2;
        float cd = cp - ct;
        float conf = cd * cd - 0.5f * cp * cp;

        local = cls + coor + conf;
    }

    // block reduction: warp shuffles + shared
    #pragma unroll
    for (int o = 16; o > 0; o >>= 1)
        local += __shfl_down_sync(0xffffffffu, local, o);

    __shared__ float wsum[THREADS / 32];
    int lane = threadIdx.x & 31;
    int wid = threadIdx.x >> 5;
    if (lane == 0) wsum[wid] = local;
    __syncthreads();

    if (wid == 0) {
        float v = (lane < THREADS / 32) ? wsum[lane] : 0.0f;
        #pragma unroll
        for (int o = 4; o > 0; o >>= 1)
            v += __shfl_down_sync(0xffffffffu, v, o);
        if (lane == 0) {
            atomicAdd(&g_acc, (double)v);
            __threadfence();
            unsigned t = atomicAdd(&g_count, 1u);
            if (t == (unsigned)(gridDim.x - 1)) {
                // last block: publish result and reset state for next replay
                result[0] = (float)(g_acc / (double)B_SZ);
                g_acc = 0.0;
                g_count = 0u;
            }
        }
    }
}

extern "C" void kernel_launch(void* const* d_in, const int* in_sizes, int n_in,
                              void* d_out, int out_size) {
    const float* output = (const float*)d_in[0];
    const float* labels = (const float*)d_in[1];
    float* out = (float*)d_out;

    yolo_loss_kernel<<<NBLOCKS, THREADS>>>(output, labels, out);
}

// round 7
// speedup vs baseline: 1.7953x; 1.7953x over previous
#include <cuda_runtime.h>

#define B_SZ    16384
#define NL      131072
#define THREADS 256
#define CELL_BLOCKS 448                // 448*256 = 114688 threads, 7 cells each
#define CELL_THREADS (CELL_BLOCKS * THREADS)   // 114688
#define LABEL_BLOCKS 512               // 512*256 = 131072 = NL
#define NBLOCKS (CELL_BLOCKS + LABEL_BLOCKS)   // 960
#define NCLS    20

__device__ double       g_acc   = 0.0;
__device__ unsigned int g_count = 0;

// evict-last cache policy (pin working set in L2 across graph replays)
__device__ __forceinline__ unsigned long long mk_policy() {
    unsigned long long pol;
    asm volatile("createpolicy.fractional.L2::evict_last.b64 %0, 1.0;" : "=l"(pol));
    return pol;
}

// float2 load, non-coherent, with L2 cache-hint policy
__device__ __forceinline__ float2 ldg_el2(const float2* __restrict__ p,
                                          unsigned long long pol) {
    float2 v;
    asm volatile("ld.global.nc.L2::cache_hint.v2.f32 {%0,%1}, [%2], %3;"
                 : "=f"(v.x), "=f"(v.y) : "l"(p), "l"(pol));
    return v;
}

__device__ __forceinline__ float iou_pair(float ax, float ay, float aw, float ah,
                                          float gx, float gy, float gw, float gh) {
    float ax1 = ax - aw * 0.5f, ax2 = ax + aw * 0.5f;
    float ay1 = ay - ah * 0.5f, ay2 = ay + ah * 0.5f;
    float gx1 = gx - gw * 0.5f, gx2 = gx + gw * 0.5f;
    float gy1 = gy - gh * 0.5f, gy2 = gy + gh * 0.5f;
    float iw = fmaxf(0.0f, fminf(ax2, gx2) - fmaxf(ax1, gx1));
    float ih = fmaxf(0.0f, fminf(ay2, gy2) - fmaxf(ay1, gy1));
    float inter = iw * ih;
    float uni = aw * ah + gw * gh - inter;
    return inter / (uni + 1e-6f);
}

__global__ void __launch_bounds__(THREADS, 8)
yolo_loss_kernel(const float* __restrict__ out, const float* __restrict__ labels,
                 float* __restrict__ result) {
    float local = 0.0f;
    const unsigned long long pol = mk_policy();

    if (blockIdx.x < CELL_BLOCKS) {
        // ---- no-object term: 7 independent strided float2 loads per thread ----
        unsigned base = blockIdx.x * THREADS + threadIdx.x;
        float2 v[7];
        #pragma unroll
        for (int k = 0; k < 7; k++) {
            unsigned cell = base + k * CELL_THREADS;
            v[k] = ldg_el2(reinterpret_cast<const float2*>(out + (size_t)cell * 30 + 20), pol);
        }
        #pragma unroll
        for (int k = 0; k < 7; k++)
            local += v[k].x * v[k].x + v[k].y * v[k].y;
        local *= 0.5f;
    } else {
        // ---- per-label term: 1 label per thread, 15-deep independent gather ----
        unsigned i = (blockIdx.x - CELL_BLOCKS) * THREADS + threadIdx.x;  // < NL
        const float2* Lp = reinterpret_cast<const float2*>(labels + (size_t)i * 6);
        float2 l0 = ldg_el2(Lp + 0, pol);   // b, cls
        float2 l1 = ldg_el2(Lp + 1, pol);   // gx, gy
        float2 l2 = ldg_el2(Lp + 2, pol);   // gw, gh
        int b = (int)l0.x;
        int c = (int)l0.y;
        float gx = l1.x, gy = l1.y, gw = l2.x, gh = l2.y;

        float rowf = floorf(gx * 7.0f);
        float colf = floorf(gy * 7.0f);
        int row = (int)rowf, col = (int)colf;

        const float2* p2 = reinterpret_cast<const float2*>(
            out + ((size_t)b * 49 + (size_t)(row * 7 + col)) * 30);

        // Batch A: channels 0..15
        float2 va[8];
        #pragma unroll
        for (int k = 0; k < 8; k++) va[k] = ldg_el2(p2 + k, pol);

        float sumsq = 0.0f;
        float pvc = 0.0f;
        #pragma unroll
        for (int k = 0; k < 8; k++) {
            sumsq += va[k].x * va[k].x + va[k].y * va[k].y;
            if (c == 2 * k)     pvc = va[k].x;
            if (c == 2 * k + 1) pvc = va[k].y;
        }

        // Batch B: channels 16..29
        float2 vb[7];
        #pragma unroll
        for (int k = 0; k < 7; k++) vb[k] = ldg_el2(p2 + 8 + k, pol);

        sumsq += vb[0].x * vb[0].x + vb[0].y * vb[0].y
               + vb[1].x * vb[1].x + vb[1].y * vb[1].y;
        if (c == 16) pvc = vb[0].x;
        if (c == 17) pvc = vb[0].y;
        if (c == 18) pvc = vb[1].x;
        if (c == 19) pvc = vb[1].y;
        float cls = sumsq - 2.0f * pvc + 1.0f;

        // channels: 20=vb[2].x 21=vb[2].y 22=vb[3].x 23=vb[3].y 24=vb[4].x
        //           25=vb[4].y 26=vb[5].x 27=vb[5].y 28=vb[6].x 29=vb[6].y
        const float inv_s = 1.0f / 7.0f;
        float iou1 = iou_pair((rowf + vb[3].x) * inv_s, (colf + vb[3].y) * inv_s,
                              vb[4].x, vb[4].y, gx, gy, gw, gh);
        float iou2 = iou_pair((rowf + vb[5].x) * inv_s, (colf + vb[5].y) * inv_s,
                              vb[6].x, vb[6].y, gx, gy, gw, gh);
        bool use1 = (iou1 >= iou2);

        float gcx = gx * 7.0f - rowf;
        float gcy = gy * 7.0f - colf;

        float px = use1 ? vb[3].x : vb[5].x;
        float py = use1 ? vb[3].y : vb[5].y;
        float pw = use1 ? vb[4].x : vb[6].x;
        float ph = use1 ? vb[4].y : vb[6].y;

        const float eps = 1e-6f;
        float dx = px - gcx;
        float dy = py - gcy;
        float dw = sqrtf(pw + eps) - sqrtf(gw + eps);
        float dh = sqrtf(ph + eps) - sqrtf(gh + eps);
        float coor = 5.0f * (dx * dx + dy * dy + dw * dw + dh * dh);

        float cp = use1 ? vb[2].x : vb[2].y;
        float ct = use1 ? iou1 : iou2;
        float cd = cp - ct;
        float conf = cd * cd - 0.5f * cp * cp;

        local = cls + coor + conf;
    }

    // block reduction: warp shuffles + shared
    #pragma unroll
    for (int o = 16; o > 0; o >>= 1)
        local += __shfl_down_sync(0xffffffffu, local, o);

    __shared__ float wsum[THREADS / 32];
    int lane = threadIdx.x & 31;
    int wid = threadIdx.x >> 5;
    if (lane == 0) wsum[wid] = local;
    __syncthreads();

    if (wid == 0) {
        float v = (lane < THREADS / 32) ? wsum[lane] : 0.0f;
        #pragma unroll
        for (int o = 4; o > 0; o >>= 1)
            v += __shfl_down_sync(0xffffffffu, v, o);
        if (lane == 0) {
            atomicAdd(&g_acc, (double)v);
            __threadfence();
            unsigned t = atomicAdd(&g_count, 1u);
            if (t == (unsigned)(gridDim.x - 1)) {
                // last block: publish result and reset state for next replay
                result[0] = (float)(g_acc / (double)B_SZ);
                g_acc = 0.0;
                g_count = 0u;
            }
        }
    }
}

extern "C" void kernel_launch(void* const* d_in, const int* in_sizes, int n_in,
                              void* d_out, int out_size) {
    const float* output = (const float*)d_in[0];
    const float* labels = (const float*)d_in[1];
    float* out = (float*)d_out;

    yolo_loss_kernel<<<NBLOCKS, THREADS>>>(output, labels, out);
}